// round 14
// baseline (speedup 1.0000x reference)
#include <cuda_runtime.h>
#include <math.h>
#include <stdint.h>

#define INC 64
#define HID 16
#define BATCHES 8
#define NMAX 300032   // N=300000 (+ pad row)

// ---- scratch (zero-initialized at module load; k_seg last block re-zeros) ----
__device__ float    g_segsum[BATCHES * INC];
__device__ unsigned g_segmax[BATCHES * INC];   // order-encoded float; 0 == identity
__device__ float    g_count[BATCHES];
__device__ float    g_gate[BATCHES * INC];
__device__ float2   g_sm[NMAX];                // (mean, max) per point, + zero pad row
__device__ float    g_sig[NMAX];               // spatial sigmoid per point
__device__ unsigned g_done;                    // k_seg completion ticket

__device__ __forceinline__ unsigned encode_ord(float f) {
    unsigned b = __float_as_uint(f);
    return (b & 0x80000000u) ? ~b : (b ^ 0x80000000u);
}
__device__ __forceinline__ float decode_ord(unsigned u) {
    unsigned b = (u & 0x80000000u) ? (u ^ 0x80000000u) : ~u;
    return __uint_as_float(b);
}

__device__ __forceinline__ void accum4(float4& sum, float4& mx, float4 v) {
    sum.x += v.x; sum.y += v.y; sum.z += v.z; sum.w += v.w;
    mx.x = fmaxf(mx.x, v.x); mx.y = fmaxf(mx.y, v.y);
    mx.z = fmaxf(mx.z, v.z); mx.w = fmaxf(mx.w, v.w);
}

__device__ __forceinline__ void flush_seg(float* s_sum, unsigned* s_max, float* s_cnt,
                                          int cur, int q, float4& sum, float4& mx,
                                          float& cnt) {
    float*    ss = &s_sum[cur * INC + q * 4];
    unsigned* sx = &s_max[cur * INC + q * 4];
    atomicAdd(ss + 0, sum.x); atomicAdd(ss + 1, sum.y);
    atomicAdd(ss + 2, sum.z); atomicAdd(ss + 3, sum.w);
    atomicMax(sx + 0, encode_ord(mx.x)); atomicMax(sx + 1, encode_ord(mx.y));
    atomicMax(sx + 2, encode_ord(mx.z)); atomicMax(sx + 3, encode_ord(mx.w));
    if (q == 0) atomicAdd(&s_cnt[cur], cnt);
    sum = make_float4(0.f, 0.f, 0.f, 0.f);
    mx  = make_float4(-INFINITY, -INFINITY, -INFINITY, -INFINITY);
    cnt = 0.f;
}

// ---- K1: segment sum/max + last-block gate MLP.
//      Fast path when the block's chunk has no batch boundary (99% of blocks). ----
__global__ __launch_bounds__(512) void k_seg(const float* __restrict__ F,
                                             const int* __restrict__ bidx, int n,
                                             const float* __restrict__ W1,
                                             const float* __restrict__ b1,
                                             const float* __restrict__ W2,
                                             const float* __restrict__ b2) {
    __shared__ float    s_sum[BATCHES * INC];
    __shared__ unsigned s_max[BATCHES * INC];
    __shared__ float    s_cnt[BATCHES];
    __shared__ int      s_islast;

    int t = threadIdx.x;
    for (int i = t; i < BATCHES * INC; i += 512) { s_sum[i] = 0.f; s_max[i] = 0u; }
    if (t < BATCHES) s_cnt[t] = 0.f;
    __syncthreads();

    int chunk = (n + gridDim.x - 1) / gridDim.x;
    int start = blockIdx.x * chunk;
    int end   = min(start + chunk, n);

    int q     = t & 15;    // channel quad
    int rlane = t >> 4;    // 0..31

    if (start < end) {
        float4 sum = make_float4(0.f, 0.f, 0.f, 0.f);
        float4 mx  = make_float4(-INFINITY, -INFINITY, -INFINITY, -INFINITY);
        float cnt = 0.f;

        int bfirst = bidx[start], blast = bidx[end - 1];
        if (bfirst == blast) {
            // ---- FAST PATH: single segment, no bidx loads, no compares ----
            int r = start + rlane * 4;
            for (; r + 3 < end; r += 128) {
                float4 v0 = ((const float4*)(F + (long)r * INC))[q];
                float4 v1 = ((const float4*)(F + (long)(r + 1) * INC))[q];
                float4 v2 = ((const float4*)(F + (long)(r + 2) * INC))[q];
                float4 v3 = ((const float4*)(F + (long)(r + 3) * INC))[q];
                accum4(sum, mx, v0); accum4(sum, mx, v1);
                accum4(sum, mx, v2); accum4(sum, mx, v3);
                cnt += 4.f;
            }
            for (int rr = r; rr < end && rr < r + 4; rr++) {
                float4 v0 = ((const float4*)(F + (long)rr * INC))[q];
                accum4(sum, mx, v0); cnt += 1.f;
            }
            if (cnt > 0.f) flush_seg(s_sum, s_max, s_cnt, bfirst, q, sum, mx, cnt);
        } else {
            // ---- SLOW PATH: per-row boundary tracking ----
            int cur = -1;
            int r = start + rlane * 4;
            for (; r + 3 < end; r += 128) {
                int b0 = bidx[r],      b1_ = bidx[r + 1];
                int b2_ = bidx[r + 2], b3  = bidx[r + 3];
                float4 v0 = ((const float4*)(F + (long)r * INC))[q];
                float4 v1 = ((const float4*)(F + (long)(r + 1) * INC))[q];
                float4 v2 = ((const float4*)(F + (long)(r + 2) * INC))[q];
                float4 v3 = ((const float4*)(F + (long)(r + 3) * INC))[q];
                if (b0 != cur) {
                    if (cur >= 0) flush_seg(s_sum, s_max, s_cnt, cur, q, sum, mx, cnt);
                    cur = b0;
                }
                accum4(sum, mx, v0); cnt += 1.f;
                if (b1_ != cur) { flush_seg(s_sum, s_max, s_cnt, cur, q, sum, mx, cnt); cur = b1_; }
                accum4(sum, mx, v1); cnt += 1.f;
                if (b2_ != cur) { flush_seg(s_sum, s_max, s_cnt, cur, q, sum, mx, cnt); cur = b2_; }
                accum4(sum, mx, v2); cnt += 1.f;
                if (b3 != cur) { flush_seg(s_sum, s_max, s_cnt, cur, q, sum, mx, cnt); cur = b3; }
                accum4(sum, mx, v3); cnt += 1.f;
            }
            for (int rr = r; rr < end && rr < r + 4; rr++) {
                int b0 = bidx[rr];
                float4 v0 = ((const float4*)(F + (long)rr * INC))[q];
                if (b0 != cur) {
                    if (cur >= 0) flush_seg(s_sum, s_max, s_cnt, cur, q, sum, mx, cnt);
                    cur = b0;
                }
                accum4(sum, mx, v0); cnt += 1.f;
            }
            if (cur >= 0) flush_seg(s_sum, s_max, s_cnt, cur, q, sum, mx, cnt);
        }
    }
    __syncthreads();

    for (int i = t; i < BATCHES * INC; i += 512) {
        int b = i >> 6;
        if (s_cnt[b] > 0.f) {
            atomicAdd(&g_segsum[i], s_sum[i]);
            atomicMax(&g_segmax[i], s_max[i]);
        }
    }
    if (t < BATCHES && s_cnt[t] > 0.f) atomicAdd(&g_count[t], s_cnt[t]);

    // ---- last-block: compute gate MLP, then reset accumulators + ticket ----
    __threadfence();
    if (t == 0) {
        unsigned v = atomicAdd(&g_done, 1u);
        s_islast = (v == gridDim.x - 1);
    }
    __syncthreads();
    if (!s_islast) return;

    __shared__ float h1a[BATCHES][HID], h1m[BATCHES][HID];
    if (t < BATCHES * HID) {
        int b = t / HID, j = t % HID;
        float sa = b1[j], sm = b1[j];
        float inv = 1.f / g_count[b];
        for (int c = 0; c < INC; c++) {
            float w    = W1[c * HID + j];
            float mean = g_segsum[b * INC + c] * inv;
            float mxv  = decode_ord(g_segmax[b * INC + c]);
            sa += mean * w;
            sm += mxv * w;
        }
        h1a[b][j] = fmaxf(sa, 0.f);
        h1m[b][j] = fmaxf(sm, 0.f);
    }
    __syncthreads();
    if (t < BATCHES * INC) {   // 512 threads cover all 512 outputs
        int b = t / INC, c = t % INC;
        float s = 2.f * b2[c];
        #pragma unroll
        for (int j = 0; j < HID; j++)
            s += (h1a[b][j] + h1m[b][j]) * W2[j * INC + c];
        g_gate[t] = 1.f / (1.f + expf(-s));
        g_segsum[t] = 0.f;       // reset accumulators for the next call
        g_segmax[t] = 0u;
    }
    if (t < BATCHES) g_count[t] = 0.f;
    if (t == 0) g_done = 0u;
}

// ---- K3: half-warp-per-row, float4, 4-row unroll for deeper MLP ----
__global__ __launch_bounds__(256) void k_sm(const float* __restrict__ F,
                                            const int* __restrict__ bidx, int n) {
    int gtid   = blockIdx.x * blockDim.x + threadIdx.x;
    if (gtid == 0) g_sm[n] = make_float2(0.f, 0.f);   // pad row
    int hw     = gtid >> 4;
    int lane16 = threadIdx.x & 15;
    int nhw    = (gridDim.x * blockDim.x) >> 4;

    int r0 = hw * 4;
    int stride = nhw * 4;
    for (; r0 + 3 < n; r0 += stride) {
        float4 f0 = ((const float4*)(F + (long)(r0 + 0) * INC))[lane16];
        float4 f1 = ((const float4*)(F + (long)(r0 + 1) * INC))[lane16];
        float4 f2 = ((const float4*)(F + (long)(r0 + 2) * INC))[lane16];
        float4 f3 = ((const float4*)(F + (long)(r0 + 3) * INC))[lane16];
        int b0 = bidx[r0], b1 = bidx[r0 + 1], b2 = bidx[r0 + 2], b3 = bidx[r0 + 3];
        float4 g0 = ((const float4*)(g_gate + b0 * INC))[lane16];
        float4 g1 = ((const float4*)(g_gate + b1 * INC))[lane16];
        float4 g2 = ((const float4*)(g_gate + b2 * INC))[lane16];
        float4 g3 = ((const float4*)(g_gate + b3 * INC))[lane16];

        float s0, s1, s2, s3, m0, m1, m2, m3;
        {
            float a = f0.x * g0.x, b = f0.y * g0.y, c = f0.z * g0.z, d = f0.w * g0.w;
            s0 = (a + b) + (c + d); m0 = fmaxf(fmaxf(a, b), fmaxf(c, d));
        }
        {
            float a = f1.x * g1.x, b = f1.y * g1.y, c = f1.z * g1.z, d = f1.w * g1.w;
            s1 = (a + b) + (c + d); m1 = fmaxf(fmaxf(a, b), fmaxf(c, d));
        }
        {
            float a = f2.x * g2.x, b = f2.y * g2.y, c = f2.z * g2.z, d = f2.w * g2.w;
            s2 = (a + b) + (c + d); m2 = fmaxf(fmaxf(a, b), fmaxf(c, d));
        }
        {
            float a = f3.x * g3.x, b = f3.y * g3.y, c = f3.z * g3.z, d = f3.w * g3.w;
            s3 = (a + b) + (c + d); m3 = fmaxf(fmaxf(a, b), fmaxf(c, d));
        }
        #pragma unroll
        for (int o = 8; o > 0; o >>= 1) {
            s0 += __shfl_xor_sync(0xffffffffu, s0, o);
            s1 += __shfl_xor_sync(0xffffffffu, s1, o);
            s2 += __shfl_xor_sync(0xffffffffu, s2, o);
            s3 += __shfl_xor_sync(0xffffffffu, s3, o);
            m0 = fmaxf(m0, __shfl_xor_sync(0xffffffffu, m0, o));
            m1 = fmaxf(m1, __shfl_xor_sync(0xffffffffu, m1, o));
            m2 = fmaxf(m2, __shfl_xor_sync(0xffffffffu, m2, o));
            m3 = fmaxf(m3, __shfl_xor_sync(0xffffffffu, m3, o));
        }
        if (lane16 == 0) {
            g_sm[r0 + 0] = make_float2(s0 * (1.f / 64.f), m0);
            g_sm[r0 + 1] = make_float2(s1 * (1.f / 64.f), m1);
            g_sm[r0 + 2] = make_float2(s2 * (1.f / 64.f), m2);
            g_sm[r0 + 3] = make_float2(s3 * (1.f / 64.f), m3);
        }
    }
    for (; r0 < n; r0++) {   // tail rows (up to 3), handled by the owning half-warp
        int b = bidx[r0];
        float4 f = ((const float4*)(F + (long)r0 * INC))[lane16];
        float4 g = ((const float4*)(g_gate + b * INC))[lane16];
        float z0 = f.x * g.x, z1 = f.y * g.y, z2 = f.z * g.z, z3 = f.w * g.w;
        float s = (z0 + z1) + (z2 + z3);
        float m = fmaxf(fmaxf(z0, z1), fmaxf(z2, z3));
        #pragma unroll
        for (int o = 8; o > 0; o >>= 1) {
            s += __shfl_xor_sync(0xffffffffu, s, o);
            m = fmaxf(m, __shfl_xor_sync(0xffffffffu, m, o));
        }
        if (lane16 == 0) g_sm[r0] = make_float2(s * (1.f / 64.f), m);
    }
}

// ---- K4: thread-per-point 27-gather conv, no smem, 64-reg budget (no spill). ----
__global__ void __launch_bounds__(256, 4)
k_conv(const int* __restrict__ nbr, const float* __restrict__ conv_w, int n) {
    int r = blockIdx.x * blockDim.x + threadIdx.x;
    if (r >= n) return;
    const int* nb = nbr + (long)r * 27;

    float p = 0.f;
    #pragma unroll
    for (int k = 0; k < 27; k++) {
        int j = nb[k];                                  // contiguous 108B per point
        float2 s = g_sm[j];                             // L2-resident gather (2.4 MB)
        p = fmaf(s.x, __ldg(conv_w + 2 * k), p);
        p = fmaf(s.y, __ldg(conv_w + 2 * k + 1), p);
    }
    g_sig[r] = 1.f / (1.f + expf(-p));
}

// ---- K5: float4 stream, 4-way ILP: out = F * gate[bidx] * sig ----
__global__ void k_mul(const float* __restrict__ F, const int* __restrict__ bidx,
                      float* __restrict__ out, int n) {
    long total = (long)n * (INC / 4);
    long quart = (total + 3) >> 2;
    long i0 = (long)blockIdx.x * blockDim.x + threadIdx.x;
    if (i0 >= quart) return;

    #pragma unroll
    for (int e = 0; e < 4; e++) {
        long i = i0 + e * quart;
        if (i < total) {
            int r  = (int)(i >> 4);
            int c4 = (int)(i & 15);
            float4 f = ((const float4*)F)[i];
            int b = bidx[r];
            float sg = g_sig[r];
            float4 g = ((const float4*)g_gate)[b * 16 + c4];
            float4 o;
            o.x = f.x * g.x * sg; o.y = f.y * g.y * sg;
            o.z = f.z * g.z * sg; o.w = f.w * g.w * sg;
            __stcs((float4*)out + i, o);
        }
    }
}

extern "C" void kernel_launch(void* const* d_in, const int* in_sizes, int n_in,
                              void* d_out, int out_size) {
    const float* F      = (const float*)d_in[0];
    const int*   bidx   = (const int*)d_in[1];
    const int*   nbr    = (const int*)d_in[2];
    const float* W1     = (const float*)d_in[3];
    const float* b1     = (const float*)d_in[4];
    const float* W2     = (const float*)d_in[5];
    const float* b2     = (const float*)d_in[6];
    const float* conv_w = (const float*)d_in[7];
    float* out = (float*)d_out;
    int n = in_sizes[1];   // batch_idx length = N

    k_seg<<<592, 512>>>(F, bidx, n, W1, b1, W2, b2);   // gate fused into last block
    k_sm<<<1184, 256>>>(F, bidx, n);
    k_conv<<<(n + 255) / 256, 256>>>(nbr, conv_w, n);

    long total4 = (long)n * (INC / 4);
    long quart  = (total4 + 3) >> 2;
    k_mul<<<(int)((quart + 255) / 256), 256>>>(F, bidx, out, n);
}

// round 15
// speedup vs baseline: 1.0329x; 1.0329x over previous
#include <cuda_runtime.h>
#include <math.h>
#include <stdint.h>

#define INC 64
#define HID 16
#define BATCHES 8
#define NMAX 300032   // N=300000 (+ pad row)

// ---- scratch (zero-initialized at module load; k_seg last block re-zeros) ----
__device__ float    g_segsum[BATCHES * INC];
__device__ unsigned g_segmax[BATCHES * INC];   // order-encoded float; 0 == identity
__device__ float    g_count[BATCHES];
__device__ float    g_gate[BATCHES * INC];
__device__ float2   g_sm[NMAX];                // (mean, max) per point, + zero pad row
__device__ float    g_sig[NMAX];               // spatial sigmoid per point
__device__ unsigned g_done;                    // k_seg completion ticket

__device__ __forceinline__ unsigned encode_ord(float f) {
    unsigned b = __float_as_uint(f);
    return (b & 0x80000000u) ? ~b : (b ^ 0x80000000u);
}
__device__ __forceinline__ float decode_ord(unsigned u) {
    unsigned b = (u & 0x80000000u) ? (u ^ 0x80000000u) : ~u;
    return __uint_as_float(b);
}

__device__ __forceinline__ void accum4(float4& sum, float4& mx, float4 v) {
    sum.x += v.x; sum.y += v.y; sum.z += v.z; sum.w += v.w;
    mx.x = fmaxf(mx.x, v.x); mx.y = fmaxf(mx.y, v.y);
    mx.z = fmaxf(mx.z, v.z); mx.w = fmaxf(mx.w, v.w);
}

__device__ __forceinline__ void flush_seg(float* s_sum, unsigned* s_max, float* s_cnt,
                                          int cur, int q, float4& sum, float4& mx,
                                          float& cnt) {
    float*    ss = &s_sum[cur * INC + q * 4];
    unsigned* sx = &s_max[cur * INC + q * 4];
    atomicAdd(ss + 0, sum.x); atomicAdd(ss + 1, sum.y);
    atomicAdd(ss + 2, sum.z); atomicAdd(ss + 3, sum.w);
    atomicMax(sx + 0, encode_ord(mx.x)); atomicMax(sx + 1, encode_ord(mx.y));
    atomicMax(sx + 2, encode_ord(mx.z)); atomicMax(sx + 3, encode_ord(mx.w));
    if (q == 0) atomicAdd(&s_cnt[cur], cnt);
    sum = make_float4(0.f, 0.f, 0.f, 0.f);
    mx  = make_float4(-INFINITY, -INFINITY, -INFINITY, -INFINITY);
    cnt = 0.f;
}

// ---- K1: segment sum/max + last-block gate MLP.
//      Fast path when the block's chunk has no batch boundary (99% of blocks). ----
__global__ __launch_bounds__(512) void k_seg(const float* __restrict__ F,
                                             const int* __restrict__ bidx, int n,
                                             const float* __restrict__ W1,
                                             const float* __restrict__ b1,
                                             const float* __restrict__ W2,
                                             const float* __restrict__ b2) {
    __shared__ float    s_sum[BATCHES * INC];
    __shared__ unsigned s_max[BATCHES * INC];
    __shared__ float    s_cnt[BATCHES];
    __shared__ int      s_islast;

    int t = threadIdx.x;
    for (int i = t; i < BATCHES * INC; i += 512) { s_sum[i] = 0.f; s_max[i] = 0u; }
    if (t < BATCHES) s_cnt[t] = 0.f;
    __syncthreads();

    int chunk = (n + gridDim.x - 1) / gridDim.x;
    int start = blockIdx.x * chunk;
    int end   = min(start + chunk, n);

    int q     = t & 15;    // channel quad
    int rlane = t >> 4;    // 0..31

    if (start < end) {
        float4 sum = make_float4(0.f, 0.f, 0.f, 0.f);
        float4 mx  = make_float4(-INFINITY, -INFINITY, -INFINITY, -INFINITY);
        float cnt = 0.f;

        int bfirst = bidx[start], blast = bidx[end - 1];
        if (bfirst == blast) {
            // ---- FAST PATH: single segment, no bidx loads, no compares ----
            int r = start + rlane * 4;
            for (; r + 3 < end; r += 128) {
                float4 v0 = ((const float4*)(F + (long)r * INC))[q];
                float4 v1 = ((const float4*)(F + (long)(r + 1) * INC))[q];
                float4 v2 = ((const float4*)(F + (long)(r + 2) * INC))[q];
                float4 v3 = ((const float4*)(F + (long)(r + 3) * INC))[q];
                accum4(sum, mx, v0); accum4(sum, mx, v1);
                accum4(sum, mx, v2); accum4(sum, mx, v3);
                cnt += 4.f;
            }
            for (int rr = r; rr < end && rr < r + 4; rr++) {
                float4 v0 = ((const float4*)(F + (long)rr * INC))[q];
                accum4(sum, mx, v0); cnt += 1.f;
            }
            if (cnt > 0.f) flush_seg(s_sum, s_max, s_cnt, bfirst, q, sum, mx, cnt);
        } else {
            // ---- SLOW PATH: per-row boundary tracking ----
            int cur = -1;
            int r = start + rlane * 4;
            for (; r + 3 < end; r += 128) {
                int b0 = bidx[r],      b1_ = bidx[r + 1];
                int b2_ = bidx[r + 2], b3  = bidx[r + 3];
                float4 v0 = ((const float4*)(F + (long)r * INC))[q];
                float4 v1 = ((const float4*)(F + (long)(r + 1) * INC))[q];
                float4 v2 = ((const float4*)(F + (long)(r + 2) * INC))[q];
                float4 v3 = ((const float4*)(F + (long)(r + 3) * INC))[q];
                if (b0 != cur) {
                    if (cur >= 0) flush_seg(s_sum, s_max, s_cnt, cur, q, sum, mx, cnt);
                    cur = b0;
                }
                accum4(sum, mx, v0); cnt += 1.f;
                if (b1_ != cur) { flush_seg(s_sum, s_max, s_cnt, cur, q, sum, mx, cnt); cur = b1_; }
                accum4(sum, mx, v1); cnt += 1.f;
                if (b2_ != cur) { flush_seg(s_sum, s_max, s_cnt, cur, q, sum, mx, cnt); cur = b2_; }
                accum4(sum, mx, v2); cnt += 1.f;
                if (b3 != cur) { flush_seg(s_sum, s_max, s_cnt, cur, q, sum, mx, cnt); cur = b3; }
                accum4(sum, mx, v3); cnt += 1.f;
            }
            for (int rr = r; rr < end && rr < r + 4; rr++) {
                int b0 = bidx[rr];
                float4 v0 = ((const float4*)(F + (long)rr * INC))[q];
                if (b0 != cur) {
                    if (cur >= 0) flush_seg(s_sum, s_max, s_cnt, cur, q, sum, mx, cnt);
                    cur = b0;
                }
                accum4(sum, mx, v0); cnt += 1.f;
            }
            if (cur >= 0) flush_seg(s_sum, s_max, s_cnt, cur, q, sum, mx, cnt);
        }
    }
    __syncthreads();

    for (int i = t; i < BATCHES * INC; i += 512) {
        int b = i >> 6;
        if (s_cnt[b] > 0.f) {
            atomicAdd(&g_segsum[i], s_sum[i]);
            atomicMax(&g_segmax[i], s_max[i]);
        }
    }
    if (t < BATCHES && s_cnt[t] > 0.f) atomicAdd(&g_count[t], s_cnt[t]);

    // ---- last-block: compute gate MLP, then reset accumulators + ticket ----
    __threadfence();
    if (t == 0) {
        unsigned v = atomicAdd(&g_done, 1u);
        s_islast = (v == gridDim.x - 1);
    }
    __syncthreads();
    if (!s_islast) return;

    __shared__ float h1a[BATCHES][HID], h1m[BATCHES][HID];
    if (t < BATCHES * HID) {
        int b = t / HID, j = t % HID;
        float sa = b1[j], sm = b1[j];
        float inv = 1.f / g_count[b];
        for (int c = 0; c < INC; c++) {
            float w    = W1[c * HID + j];
            float mean = g_segsum[b * INC + c] * inv;
            float mxv  = decode_ord(g_segmax[b * INC + c]);
            sa += mean * w;
            sm += mxv * w;
        }
        h1a[b][j] = fmaxf(sa, 0.f);
        h1m[b][j] = fmaxf(sm, 0.f);
    }
    __syncthreads();
    if (t < BATCHES * INC) {   // 512 threads cover all 512 outputs
        int b = t / INC, c = t % INC;
        float s = 2.f * b2[c];
        #pragma unroll
        for (int j = 0; j < HID; j++)
            s += (h1a[b][j] + h1m[b][j]) * W2[j * INC + c];
        g_gate[t] = 1.f / (1.f + expf(-s));
        g_segsum[t] = 0.f;       // reset accumulators for the next call
        g_segmax[t] = 0u;
    }
    if (t < BATCHES) g_count[t] = 0.f;
    if (t == 0) g_done = 0u;
}

// ---- K3: half-warp-per-row, float4, 2-row unroll (round-13 shape),
//      REVERSED block order: read tail of F first (freshest in L2 after k_seg). ----
__global__ __launch_bounds__(256) void k_sm(const float* __restrict__ F,
                                            const int* __restrict__ bidx, int n) {
    if (blockIdx.x == 0 && threadIdx.x == 0) g_sm[n] = make_float2(0.f, 0.f); // pad row
    int rb     = gridDim.x - 1 - blockIdx.x;           // reversed block index
    int gtid   = rb * blockDim.x + threadIdx.x;
    int hw     = gtid >> 4;
    int lane16 = threadIdx.x & 15;
    int nhw    = (gridDim.x * blockDim.x) >> 4;

    int r0 = hw * 2;
    int stride = nhw * 2;
    for (; r0 + 1 < n; r0 += stride) {
        int r1 = r0 + 1;
        int b0 = bidx[r0], b1 = bidx[r1];
        float4 fA = ((const float4*)(F + (long)r0 * INC))[lane16];
        float4 fB = ((const float4*)(F + (long)r1 * INC))[lane16];
        float4 gA = ((const float4*)(g_gate + b0 * INC))[lane16];
        float4 gB = ((const float4*)(g_gate + b1 * INC))[lane16];
        float a0 = fA.x * gA.x, a1 = fA.y * gA.y, a2 = fA.z * gA.z, a3 = fA.w * gA.w;
        float c0 = fB.x * gB.x, c1 = fB.y * gB.y, c2 = fB.z * gB.z, c3 = fB.w * gB.w;
        float sA = (a0 + a1) + (a2 + a3);
        float mA = fmaxf(fmaxf(a0, a1), fmaxf(a2, a3));
        float sB = (c0 + c1) + (c2 + c3);
        float mB = fmaxf(fmaxf(c0, c1), fmaxf(c2, c3));
        #pragma unroll
        for (int o = 8; o > 0; o >>= 1) {
            sA += __shfl_xor_sync(0xffffffffu, sA, o);
            sB += __shfl_xor_sync(0xffffffffu, sB, o);
            mA = fmaxf(mA, __shfl_xor_sync(0xffffffffu, mA, o));
            mB = fmaxf(mB, __shfl_xor_sync(0xffffffffu, mB, o));
        }
        if (lane16 == 0) {
            g_sm[r0] = make_float2(sA * (1.f / 64.f), mA);
            g_sm[r1] = make_float2(sB * (1.f / 64.f), mB);
        }
    }
    if (r0 < n) {   // tail
        int b = bidx[r0];
        float4 f = ((const float4*)(F + (long)r0 * INC))[lane16];
        float4 g = ((const float4*)(g_gate + b * INC))[lane16];
        float z0 = f.x * g.x, z1 = f.y * g.y, z2 = f.z * g.z, z3 = f.w * g.w;
        float s = (z0 + z1) + (z2 + z3);
        float m = fmaxf(fmaxf(z0, z1), fmaxf(z2, z3));
        #pragma unroll
        for (int o = 8; o > 0; o >>= 1) {
            s += __shfl_xor_sync(0xffffffffu, s, o);
            m = fmaxf(m, __shfl_xor_sync(0xffffffffu, m, o));
        }
        if (lane16 == 0) g_sm[r0] = make_float2(s * (1.f / 64.f), m);
    }
}

// ---- K4: thread-per-point 27-gather conv, no smem, 64-reg budget (no spill). ----
__global__ void __launch_bounds__(256, 4)
k_conv(const int* __restrict__ nbr, const float* __restrict__ conv_w, int n) {
    int r = blockIdx.x * blockDim.x + threadIdx.x;
    if (r >= n) return;
    const int* nb = nbr + (long)r * 27;

    float p = 0.f;
    #pragma unroll
    for (int k = 0; k < 27; k++) {
        int j = nb[k];                                  // contiguous 108B per point
        float2 s = g_sm[j];                             // L2-resident gather (2.4 MB)
        p = fmaf(s.x, __ldg(conv_w + 2 * k), p);
        p = fmaf(s.y, __ldg(conv_w + 2 * k + 1), p);
    }
    g_sig[r] = 1.f / (1.f + expf(-p));
}

// ---- K5: float4 stream, 2-element ILP (round-13 shape): out = F*gate*sig ----
__global__ void k_mul(const float* __restrict__ F, const int* __restrict__ bidx,
                      float* __restrict__ out, int n) {
    long total = (long)n * (INC / 4);
    long half  = (total + 1) >> 1;
    long i = (long)blockIdx.x * blockDim.x + threadIdx.x;
    if (i >= half) return;
    long i2 = i + half;

    int r  = (int)(i >> 4);
    int c4 = (int)(i & 15);
    float4 f = ((const float4*)F)[i];
    int b = bidx[r];
    float sg = g_sig[r];

    float4 f2; int b2i = 0; float sg2 = 0.f; int r2 = 0, c42 = 0;
    bool have2 = (i2 < total);
    if (have2) {
        r2  = (int)(i2 >> 4);
        c42 = (int)(i2 & 15);
        f2  = ((const float4*)F)[i2];
        b2i = bidx[r2];
        sg2 = g_sig[r2];
    }

    float4 g = ((const float4*)g_gate)[b * 16 + c4];
    float4 o;
    o.x = f.x * g.x * sg; o.y = f.y * g.y * sg;
    o.z = f.z * g.z * sg; o.w = f.w * g.w * sg;
    __stcs((float4*)out + i, o);

    if (have2) {
        float4 g2 = ((const float4*)g_gate)[b2i * 16 + c42];
        float4 o2;
        o2.x = f2.x * g2.x * sg2; o2.y = f2.y * g2.y * sg2;
        o2.z = f2.z * g2.z * sg2; o2.w = f2.w * g2.w * sg2;
        __stcs((float4*)out + i2, o2);
    }
}

extern "C" void kernel_launch(void* const* d_in, const int* in_sizes, int n_in,
                              void* d_out, int out_size) {
    const float* F      = (const float*)d_in[0];
    const int*   bidx   = (const int*)d_in[1];
    const int*   nbr    = (const int*)d_in[2];
    const float* W1     = (const float*)d_in[3];
    const float* b1     = (const float*)d_in[4];
    const float* W2     = (const float*)d_in[5];
    const float* b2     = (const float*)d_in[6];
    const float* conv_w = (const float*)d_in[7];
    float* out = (float*)d_out;
    int n = in_sizes[1];   // batch_idx length = N

    k_seg<<<592, 512>>>(F, bidx, n, W1, b1, W2, b2);   // gate fused into last block
    k_sm<<<1184, 256>>>(F, bidx, n);
    k_conv<<<(n + 255) / 256, 256>>>(nbr, conv_w, n);

    long total4 = (long)n * (INC / 4);
    long half   = (total4 + 1) >> 1;
    k_mul<<<(int)((half + 255) / 256), 256>>>(F, bidx, out, n);
}

// round 16
// speedup vs baseline: 1.0753x; 1.0410x over previous
#include <cuda_runtime.h>
#include <math.h>
#include <stdint.h>

#define INC 64
#define HID 16
#define BATCHES 8
#define NMAX 300032   // N=300000 (+ pad row)

// ---- scratch (zero-initialized at module load; k_seg last block re-zeros) ----
__device__ float    g_segsum[BATCHES * INC];
__device__ unsigned g_segmax[BATCHES * INC];   // order-encoded float; 0 == identity
__device__ float    g_count[BATCHES];
__device__ float    g_gate[BATCHES * INC];
__device__ float2   g_sm[NMAX];                // (mean, max) per point, + zero pad row
__device__ unsigned g_done;                    // k_seg completion ticket

__device__ __forceinline__ unsigned encode_ord(float f) {
    unsigned b = __float_as_uint(f);
    return (b & 0x80000000u) ? ~b : (b ^ 0x80000000u);
}
__device__ __forceinline__ float decode_ord(unsigned u) {
    unsigned b = (u & 0x80000000u) ? (u ^ 0x80000000u) : ~u;
    return __uint_as_float(b);
}

__device__ __forceinline__ void accum4(float4& sum, float4& mx, float4 v) {
    sum.x += v.x; sum.y += v.y; sum.z += v.z; sum.w += v.w;
    mx.x = fmaxf(mx.x, v.x); mx.y = fmaxf(mx.y, v.y);
    mx.z = fmaxf(mx.z, v.z); mx.w = fmaxf(mx.w, v.w);
}

__device__ __forceinline__ void flush_seg(float* s_sum, unsigned* s_max, float* s_cnt,
                                          int cur, int q, float4& sum, float4& mx,
                                          float& cnt) {
    float*    ss = &s_sum[cur * INC + q * 4];
    unsigned* sx = &s_max[cur * INC + q * 4];
    atomicAdd(ss + 0, sum.x); atomicAdd(ss + 1, sum.y);
    atomicAdd(ss + 2, sum.z); atomicAdd(ss + 3, sum.w);
    atomicMax(sx + 0, encode_ord(mx.x)); atomicMax(sx + 1, encode_ord(mx.y));
    atomicMax(sx + 2, encode_ord(mx.z)); atomicMax(sx + 3, encode_ord(mx.w));
    if (q == 0) atomicAdd(&s_cnt[cur], cnt);
    sum = make_float4(0.f, 0.f, 0.f, 0.f);
    mx  = make_float4(-INFINITY, -INFINITY, -INFINITY, -INFINITY);
    cnt = 0.f;
}

// ---- K1: segment sum/max + last-block gate MLP.
//      Fast path when the block's chunk has no batch boundary (99% of blocks). ----
__global__ __launch_bounds__(512) void k_seg(const float* __restrict__ F,
                                             const int* __restrict__ bidx, int n,
                                             const float* __restrict__ W1,
                                             const float* __restrict__ b1,
                                             const float* __restrict__ W2,
                                             const float* __restrict__ b2) {
    __shared__ float    s_sum[BATCHES * INC];
    __shared__ unsigned s_max[BATCHES * INC];
    __shared__ float    s_cnt[BATCHES];
    __shared__ int      s_islast;

    int t = threadIdx.x;
    for (int i = t; i < BATCHES * INC; i += 512) { s_sum[i] = 0.f; s_max[i] = 0u; }
    if (t < BATCHES) s_cnt[t] = 0.f;
    __syncthreads();

    int chunk = (n + gridDim.x - 1) / gridDim.x;
    int start = blockIdx.x * chunk;
    int end   = min(start + chunk, n);

    int q     = t & 15;    // channel quad
    int rlane = t >> 4;    // 0..31

    if (start < end) {
        float4 sum = make_float4(0.f, 0.f, 0.f, 0.f);
        float4 mx  = make_float4(-INFINITY, -INFINITY, -INFINITY, -INFINITY);
        float cnt = 0.f;

        int bfirst = bidx[start], blast = bidx[end - 1];
        if (bfirst == blast) {
            // ---- FAST PATH: single segment, no bidx loads, no compares ----
            int r = start + rlane * 4;
            for (; r + 3 < end; r += 128) {
                float4 v0 = ((const float4*)(F + (long)r * INC))[q];
                float4 v1 = ((const float4*)(F + (long)(r + 1) * INC))[q];
                float4 v2 = ((const float4*)(F + (long)(r + 2) * INC))[q];
                float4 v3 = ((const float4*)(F + (long)(r + 3) * INC))[q];
                accum4(sum, mx, v0); accum4(sum, mx, v1);
                accum4(sum, mx, v2); accum4(sum, mx, v3);
                cnt += 4.f;
            }
            for (int rr = r; rr < end && rr < r + 4; rr++) {
                float4 v0 = ((const float4*)(F + (long)rr * INC))[q];
                accum4(sum, mx, v0); cnt += 1.f;
            }
            if (cnt > 0.f) flush_seg(s_sum, s_max, s_cnt, bfirst, q, sum, mx, cnt);
        } else {
            // ---- SLOW PATH: per-row boundary tracking ----
            int cur = -1;
            int r = start + rlane * 4;
            for (; r + 3 < end; r += 128) {
                int b0 = bidx[r],      b1_ = bidx[r + 1];
                int b2_ = bidx[r + 2], b3  = bidx[r + 3];
                float4 v0 = ((const float4*)(F + (long)r * INC))[q];
                float4 v1 = ((const float4*)(F + (long)(r + 1) * INC))[q];
                float4 v2 = ((const float4*)(F + (long)(r + 2) * INC))[q];
                float4 v3 = ((const float4*)(F + (long)(r + 3) * INC))[q];
                if (b0 != cur) {
                    if (cur >= 0) flush_seg(s_sum, s_max, s_cnt, cur, q, sum, mx, cnt);
                    cur = b0;
                }
                accum4(sum, mx, v0); cnt += 1.f;
                if (b1_ != cur) { flush_seg(s_sum, s_max, s_cnt, cur, q, sum, mx, cnt); cur = b1_; }
                accum4(sum, mx, v1); cnt += 1.f;
                if (b2_ != cur) { flush_seg(s_sum, s_max, s_cnt, cur, q, sum, mx, cnt); cur = b2_; }
                accum4(sum, mx, v2); cnt += 1.f;
                if (b3 != cur) { flush_seg(s_sum, s_max, s_cnt, cur, q, sum, mx, cnt); cur = b3; }
                accum4(sum, mx, v3); cnt += 1.f;
            }
            for (int rr = r; rr < end && rr < r + 4; rr++) {
                int b0 = bidx[rr];
                float4 v0 = ((const float4*)(F + (long)rr * INC))[q];
                if (b0 != cur) {
                    if (cur >= 0) flush_seg(s_sum, s_max, s_cnt, cur, q, sum, mx, cnt);
                    cur = b0;
                }
                accum4(sum, mx, v0); cnt += 1.f;
            }
            if (cur >= 0) flush_seg(s_sum, s_max, s_cnt, cur, q, sum, mx, cnt);
        }
    }
    __syncthreads();

    for (int i = t; i < BATCHES * INC; i += 512) {
        int b = i >> 6;
        if (s_cnt[b] > 0.f) {
            atomicAdd(&g_segsum[i], s_sum[i]);
            atomicMax(&g_segmax[i], s_max[i]);
        }
    }
    if (t < BATCHES && s_cnt[t] > 0.f) atomicAdd(&g_count[t], s_cnt[t]);

    // ---- last-block: compute gate MLP, then reset accumulators + ticket ----
    __threadfence();
    if (t == 0) {
        unsigned v = atomicAdd(&g_done, 1u);
        s_islast = (v == gridDim.x - 1);
    }
    __syncthreads();
    if (!s_islast) return;

    __shared__ float h1a[BATCHES][HID], h1m[BATCHES][HID];
    if (t < BATCHES * HID) {
        int b = t / HID, j = t % HID;
        float sa = b1[j], sm = b1[j];
        float inv = 1.f / g_count[b];
        for (int c = 0; c < INC; c++) {
            float w    = W1[c * HID + j];
            float mean = g_segsum[b * INC + c] * inv;
            float mxv  = decode_ord(g_segmax[b * INC + c]);
            sa += mean * w;
            sm += mxv * w;
        }
        h1a[b][j] = fmaxf(sa, 0.f);
        h1m[b][j] = fmaxf(sm, 0.f);
    }
    __syncthreads();
    if (t < BATCHES * INC) {   // 512 threads cover all 512 outputs
        int b = t / INC, c = t % INC;
        float s = 2.f * b2[c];
        #pragma unroll
        for (int j = 0; j < HID; j++)
            s += (h1a[b][j] + h1m[b][j]) * W2[j * INC + c];
        g_gate[t] = 1.f / (1.f + expf(-s));
        g_segsum[t] = 0.f;       // reset accumulators for the next call
        g_segmax[t] = 0u;
    }
    if (t < BATCHES) g_count[t] = 0.f;
    if (t == 0) g_done = 0u;
}

// ---- K3: half-warp-per-row, float4, 2-row unroll,
//      REVERSED block order: read tail of F first (freshest in L2 after k_seg). ----
__global__ __launch_bounds__(256) void k_sm(const float* __restrict__ F,
                                            const int* __restrict__ bidx, int n) {
    if (blockIdx.x == 0 && threadIdx.x == 0) g_sm[n] = make_float2(0.f, 0.f); // pad row
    int rb     = gridDim.x - 1 - blockIdx.x;           // reversed block index
    int gtid   = rb * blockDim.x + threadIdx.x;
    int hw     = gtid >> 4;
    int lane16 = threadIdx.x & 15;
    int nhw    = (gridDim.x * blockDim.x) >> 4;

    int r0 = hw * 2;
    int stride = nhw * 2;
    for (; r0 + 1 < n; r0 += stride) {
        int r1 = r0 + 1;
        int b0 = bidx[r0], b1 = bidx[r1];
        float4 fA = ((const float4*)(F + (long)r0 * INC))[lane16];
        float4 fB = ((const float4*)(F + (long)r1 * INC))[lane16];
        float4 gA = ((const float4*)(g_gate + b0 * INC))[lane16];
        float4 gB = ((const float4*)(g_gate + b1 * INC))[lane16];
        float a0 = fA.x * gA.x, a1 = fA.y * gA.y, a2 = fA.z * gA.z, a3 = fA.w * gA.w;
        float c0 = fB.x * gB.x, c1 = fB.y * gB.y, c2 = fB.z * gB.z, c3 = fB.w * gB.w;
        float sA = (a0 + a1) + (a2 + a3);
        float mA = fmaxf(fmaxf(a0, a1), fmaxf(a2, a3));
        float sB = (c0 + c1) + (c2 + c3);
        float mB = fmaxf(fmaxf(c0, c1), fmaxf(c2, c3));
        #pragma unroll
        for (int o = 8; o > 0; o >>= 1) {
            sA += __shfl_xor_sync(0xffffffffu, sA, o);
            sB += __shfl_xor_sync(0xffffffffu, sB, o);
            mA = fmaxf(mA, __shfl_xor_sync(0xffffffffu, mA, o));
            mB = fmaxf(mB, __shfl_xor_sync(0xffffffffu, mB, o));
        }
        if (lane16 == 0) {
            g_sm[r0] = make_float2(sA * (1.f / 64.f), mA);
            g_sm[r1] = make_float2(sB * (1.f / 64.f), mB);
        }
    }
    if (r0 < n) {   // tail
        int b = bidx[r0];
        float4 f = ((const float4*)(F + (long)r0 * INC))[lane16];
        float4 g = ((const float4*)(g_gate + b * INC))[lane16];
        float z0 = f.x * g.x, z1 = f.y * g.y, z2 = f.z * g.z, z3 = f.w * g.w;
        float s = (z0 + z1) + (z2 + z3);
        float m = fmaxf(fmaxf(z0, z1), fmaxf(z2, z3));
        #pragma unroll
        for (int o = 8; o > 0; o >>= 1) {
            s += __shfl_xor_sync(0xffffffffu, s, o);
            m = fmaxf(m, __shfl_xor_sync(0xffffffffu, m, o));
        }
        if (lane16 == 0) g_sm[r0] = make_float2(s * (1.f / 64.f), m);
    }
}

// ---- K4: FUSED conv+mul, half-warp per row, no smem, no block barriers.
//      Lane l16: gathers nbr l16 (+ l16+16) -> butterfly sig -> streams one float4. ----
__global__ __launch_bounds__(256) void k_convmul(const float* __restrict__ F,
                                                 const int* __restrict__ bidx,
                                                 const int* __restrict__ nbr,
                                                 const float* __restrict__ conv_w,
                                                 float* __restrict__ out, int n) {
    int gtid = blockIdx.x * blockDim.x + threadIdx.x;
    int r    = gtid >> 4;                   // half-warp id == row
    int l16  = threadIdx.x & 15;
    int rc   = min(r, n - 1);               // clamp so all lanes stay converged

    // issue the streaming F load FIRST (hides the gather chain)
    float4 f = ((const float4*)F)[(long)rc * 16 + l16];
    int b = bidx[rc];

    // spatial conv: 27 gathers split across 16 lanes
    const int* nb = nbr + (long)rc * 27;
    int j0 = __ldcs(nb + l16);                               // stream nbr: keep F in L2
    float2 s0 = g_sm[j0];
    float p = s0.x * __ldg(conv_w + 2 * l16)
            + s0.y * __ldg(conv_w + 2 * l16 + 1);
    if (l16 < 11) {
        int j1 = __ldcs(nb + 16 + l16);
        float2 s1 = g_sm[j1];
        p += s1.x * __ldg(conv_w + 32 + 2 * l16)
           + s1.y * __ldg(conv_w + 33 + 2 * l16);
    }
    #pragma unroll
    for (int o = 8; o > 0; o >>= 1)                          // stays within half-warp
        p += __shfl_xor_sync(0xffffffffu, p, o);
    float sig = 1.f / (1.f + expf(-p));

    float4 g = ((const float4*)g_gate)[b * 16 + l16];
    if (r < n) {
        float4 o4;
        o4.x = f.x * g.x * sig; o4.y = f.y * g.y * sig;
        o4.z = f.z * g.z * sig; o4.w = f.w * g.w * sig;
        __stcs((float4*)out + (long)r * 16 + l16, o4);
    }
}

extern "C" void kernel_launch(void* const* d_in, const int* in_sizes, int n_in,
                              void* d_out, int out_size) {
    const float* F      = (const float*)d_in[0];
    const int*   bidx   = (const int*)d_in[1];
    const int*   nbr    = (const int*)d_in[2];
    const float* W1     = (const float*)d_in[3];
    const float* b1     = (const float*)d_in[4];
    const float* W2     = (const float*)d_in[5];
    const float* b2     = (const float*)d_in[6];
    const float* conv_w = (const float*)d_in[7];
    float* out = (float*)d_out;
    int n = in_sizes[1];   // batch_idx length = N

    k_seg<<<592, 512>>>(F, bidx, n, W1, b1, W2, b2);   // gate fused into last block
    k_sm<<<1184, 256>>>(F, bidx, n);

    long threads = (long)n * 16;                        // one half-warp per row
    k_convmul<<<(int)((threads + 255) / 256), 256>>>(F, bidx, nbr, conv_w, out, n);
}